// round 9
// baseline (speedup 1.0000x reference)
#include <cuda_runtime.h>
#include <cuda_bf16.h>
#include <math.h>

// ---------------- problem constants ----------------
#define BATCH 64
#define HDIM  2048
#define SEQ   2048
#define NH    32
#define NKV   4
#define GQA   8          // NH/NKV
#define HD    128
#define NEXP  32
#define IDIM  768
#define TOPK  4
#define QKV_N 5120       // (NH+2*NKV)*HD
#define EPS   1e-6f
#define SCHUNK 256
#define NCHUNK (SEQ / SCHUNK)   // 8
#define PD 4                    // GEMM pipeline depth

// ---------------- scratch (device globals) ----------------
// Scratch passed as kernel ARGUMENTS must be resolved via cudaGetSymbolAddress
// (host &g_x is the ATS host shadow — rounds 1-5 bug). In-kernel refs ok.
__device__ float g_hn   [BATCH * HDIM];
__device__ float g_qkv  [BATCH * QKV_N];
__device__ float g_attn [BATCH * NH * HD];
__device__ float g_hs2  [BATCH * HDIM];
__device__ float g_h2   [BATCH * HDIM];
__device__ float g_act  [NEXP * BATCH * IDIM];
__device__ float g_ypair[BATCH * TOPK * HDIM];
__device__ float g_part [8 * BATCH * QKV_N / 2];
__device__ int   g_cnt  [NEXP];
__device__ int   g_tok  [NEXP * BATCH];
__device__ int   g_slot [NEXP * BATCH];
__device__ float g_wt   [NEXP * BATCH];
// split-S attention partials
__device__ float g_pm [BATCH * NKV * NCHUNK * GQA];
__device__ float g_pl [BATCH * NKV * NCHUNK * GQA];
__device__ float g_po [BATCH * NKV * NCHUNK * GQA * HD];

// ---------------- reset routing counters ----------------
__global__ void reset_k() {
    if (threadIdx.x < NEXP) g_cnt[threadIdx.x] = 0;
}

// ---------------- RMSNorm (block per token) ----------------
__global__ __launch_bounds__(256) void rmsnorm_k(
    const float* __restrict__ x, const float* __restrict__ w, float* __restrict__ y)
{
    int b = blockIdx.x, tid = threadIdx.x;
    const float* xb = x + b * HDIM;
    float s = 0.f;
    for (int i = tid; i < HDIM; i += 256) { float v = xb[i]; s += v * v; }
    for (int o = 16; o; o >>= 1) s += __shfl_xor_sync(0xffffffffu, s, o);
    __shared__ float red[8];
    __shared__ float inv;
    if ((tid & 31) == 0) red[tid >> 5] = s;
    __syncthreads();
    if (tid == 0) {
        float t = 0.f;
        #pragma unroll
        for (int i = 0; i < 8; i++) t += red[i];
        inv = rsqrtf(t * (1.f / HDIM) + EPS);
    }
    __syncthreads();
    float iv = inv;
    for (int i = tid; i < HDIM; i += 256) y[b * HDIM + i] = xb[i] * iv * w[i];
}

// ---------------- GEMM partial: 4-deep pipelined, BM=64 BN=64 BK=16 ----------------
__global__ __launch_bounds__(256) void gemm_part_k(
    const float* __restrict__ A, const float* __restrict__ W,
    float* __restrict__ part, int N, int K, int ksplit)
{
    __shared__ float As[PD][16][68];
    __shared__ float Ws[PD][16][68];
    int nb = blockIdx.x * 64;
    int ks = blockIdx.y;
    int klen = K / ksplit;
    int kbeg = ks * klen;
    int tiles = klen / 16;
    int tid = threadIdx.x;

    int lm = tid >> 2;            // 0..63
    int lk = (tid & 3) * 4;       // 0,4,8,12
    const float* Ag = A + (long)lm * K + kbeg + lk;
    const float* Wg = W + (long)(nb + lm) * K + kbeg + lk;

    int tx = tid & 15, ty = tid >> 4;
    float acc[4][4] = {};

    float4 rA[PD], rW[PD];
    #pragma unroll
    for (int s = 0; s < PD; s++) {
        if (s < tiles) {
            rA[s] = *(const float4*)(Ag + s * 16);
            rW[s] = *(const float4*)(Wg + s * 16);
        }
    }

    for (int t = 0; t < tiles; t++) {
        int buf = t & (PD - 1);
        As[buf][lk+0][lm] = rA[buf].x; As[buf][lk+1][lm] = rA[buf].y;
        As[buf][lk+2][lm] = rA[buf].z; As[buf][lk+3][lm] = rA[buf].w;
        Ws[buf][lk+0][lm] = rW[buf].x; Ws[buf][lk+1][lm] = rW[buf].y;
        Ws[buf][lk+2][lm] = rW[buf].z; Ws[buf][lk+3][lm] = rW[buf].w;
        if (t + PD < tiles) {
            rA[buf] = *(const float4*)(Ag + (t + PD) * 16);
            rW[buf] = *(const float4*)(Wg + (t + PD) * 16);
        }
        __syncthreads();
        #pragma unroll
        for (int kk = 0; kk < 16; kk++) {
            float4 a = *(const float4*)&As[buf][kk][ty * 4];
            float4 w = *(const float4*)&Ws[buf][kk][tx * 4];
            acc[0][0] = fmaf(a.x, w.x, acc[0][0]); acc[0][1] = fmaf(a.x, w.y, acc[0][1]);
            acc[0][2] = fmaf(a.x, w.z, acc[0][2]); acc[0][3] = fmaf(a.x, w.w, acc[0][3]);
            acc[1][0] = fmaf(a.y, w.x, acc[1][0]); acc[1][1] = fmaf(a.y, w.y, acc[1][1]);
            acc[1][2] = fmaf(a.y, w.z, acc[1][2]); acc[1][3] = fmaf(a.y, w.w, acc[1][3]);
            acc[2][0] = fmaf(a.z, w.x, acc[2][0]); acc[2][1] = fmaf(a.z, w.y, acc[2][1]);
            acc[2][2] = fmaf(a.z, w.z, acc[2][2]); acc[2][3] = fmaf(a.z, w.w, acc[2][3]);
            acc[3][0] = fmaf(a.w, w.x, acc[3][0]); acc[3][1] = fmaf(a.w, w.y, acc[3][1]);
            acc[3][2] = fmaf(a.w, w.z, acc[3][2]); acc[3][3] = fmaf(a.w, w.w, acc[3][3]);
        }
        __syncthreads();
    }

    #pragma unroll
    for (int i = 0; i < 4; i++) {
        float4 v = make_float4(acc[i][0], acc[i][1], acc[i][2], acc[i][3]);
        *(float4*)&part[((long)(ks * 64 + ty * 4 + i)) * N + nb + tx * 4] = v;
    }
}

// ---------------- GEMM reduce: C = sum_ks part + bias (+res) ----------------
__global__ __launch_bounds__(256) void gemm_reduce_k(
    const float* __restrict__ part, const float* __restrict__ bias,
    const float* __restrict__ res, float* __restrict__ C, int N, int ksplit)
{
    int idx = (blockIdx.x * 256 + threadIdx.x) * 4;
    int m = idx / N, n = idx % N;
    float4 s = bias ? *(const float4*)&bias[n] : make_float4(0.f, 0.f, 0.f, 0.f);
    for (int ks = 0; ks < ksplit; ks++) {
        float4 p = *(const float4*)&part[((long)(ks * 64 + m)) * N + n];
        s.x += p.x; s.y += p.y; s.z += p.z; s.w += p.w;
    }
    if (res) {
        float4 r = *(const float4*)&res[idx];
        s.x += r.x; s.y += r.y; s.z += r.z; s.w += r.w;
    }
    *(float4*)&C[idx] = s;
}

// ---------------- split-S GQA flash-decode: partial per (b, kv, chunk) ----------------
__global__ __launch_bounds__(256) void attn_part_k(
    const float* __restrict__ kc, const float* __restrict__ vc,
    const int* __restrict__ seq_lens)
{
    int c  = blockIdx.x;
    int kv = blockIdx.y;
    int b  = blockIdx.z;
    int tid = threadIdx.x, warp = tid >> 5, lane = tid & 31;
    int sl = seq_lens[b];
    if (sl < 0) sl = 0;
    if (sl > SEQ - 1) sl = SEQ - 1;
    int L  = sl + 1;
    int s0 = c * SCHUNK;
    if (s0 >= L) return;
    int s1 = s0 + SCHUNK; if (s1 > L) s1 = L;
    const float scale = 0.08838834764831845f;

    const float* qbase = g_qkv + b * QKV_N + kv * GQA * HD;
    const float* knew  = g_qkv + b * QKV_N + NH * HD + kv * HD;
    const float* vnew  = g_qkv + b * QKV_N + (NH + NKV) * HD + kv * HD;

    float4 q[GQA];
    #pragma unroll
    for (int h = 0; h < GQA; h++) q[h] = *(const float4*)(qbase + h * HD + lane * 4);

    float m[GQA], l[GQA];
    float4 o[GQA];
    #pragma unroll
    for (int h = 0; h < GQA; h++) {
        m[h] = -INFINITY; l[h] = 0.f; o[h] = make_float4(0.f, 0.f, 0.f, 0.f);
    }

    int s = s0 + warp;
    if (s < s1) {
        const float* kp = (s == sl) ? knew : (kc + ((size_t)(b * SEQ + s) * NKV + kv) * HD);
        const float* vp = (s == sl) ? vnew : (vc + ((size_t)(b * SEQ + s) * NKV + kv) * HD);
        float4 kk = *(const float4*)(kp + lane * 4);
        float4 vv = *(const float4*)(vp + lane * 4);
        for (;;) {
            int sn = s + 8;
            float4 knx, vnx;
            if (sn < s1) {
                const float* kp2 = (sn == sl) ? knew : (kc + ((size_t)(b * SEQ + sn) * NKV + kv) * HD);
                const float* vp2 = (sn == sl) ? vnew : (vc + ((size_t)(b * SEQ + sn) * NKV + kv) * HD);
                knx = *(const float4*)(kp2 + lane * 4);
                vnx = *(const float4*)(vp2 + lane * 4);
            }
            #pragma unroll
            for (int h = 0; h < GQA; h++) {
                float d = q[h].x * kk.x + q[h].y * kk.y + q[h].z * kk.z + q[h].w * kk.w;
                d += __shfl_xor_sync(0xffffffffu, d, 16);
                d += __shfl_xor_sync(0xffffffffu, d, 8);
                d += __shfl_xor_sync(0xffffffffu, d, 4);
                d += __shfl_xor_sync(0xffffffffu, d, 2);
                d += __shfl_xor_sync(0xffffffffu, d, 1);
                float sc = d * scale;
                float nm = fmaxf(m[h], sc);
                float corr = __expf(m[h] - nm);
                float p = __expf(sc - nm);
                l[h] = l[h] * corr + p;
                o[h].x = o[h].x * corr + p * vv.x;
                o[h].y = o[h].y * corr + p * vv.y;
                o[h].z = o[h].z * corr + p * vv.z;
                o[h].w = o[h].w * corr + p * vv.w;
                m[h] = nm;
            }
            if (sn >= s1) break;
            s = sn; kk = knx; vv = vnx;
        }
    }

    __shared__ float sm[8][GQA], sll[8][GQA];
    __shared__ float so[8][GQA][HD];
    #pragma unroll
    for (int h = 0; h < GQA; h++) {
        if (lane == 0) { sm[warp][h] = m[h]; sll[warp][h] = l[h]; }
        *(float4*)&so[warp][h][lane * 4] = o[h];
    }
    __syncthreads();

    int pbase = ((b * NKV + kv) * NCHUNK + c) * GQA;
    for (int idx = tid; idx < GQA * HD; idx += 256) {
        int h = idx >> 7, d = idx & (HD - 1);
        float M = -INFINITY;
        #pragma unroll
        for (int w = 0; w < 8; w++) M = fmaxf(M, sm[w][h]);
        float acc = 0.f, Ls = 0.f;
        #pragma unroll
        for (int w = 0; w < 8; w++) {
            float cw = __expf(sm[w][h] - M);
            acc += cw * so[w][h][d];
            Ls  += cw * sll[w][h];
        }
        g_po[(pbase + h) * HD + d] = acc;
        if (d == 0) { g_pm[pbase + h] = M; g_pl[pbase + h] = Ls; }
    }
}

// ---------------- combine split-S partials ----------------
__global__ __launch_bounds__(256) void attn_comb_k(
    const int* __restrict__ seq_lens, float* __restrict__ out)
{
    int b  = blockIdx.x >> 2;
    int kv = blockIdx.x & 3;
    int tid = threadIdx.x;
    int sl = seq_lens[b];
    if (sl < 0) sl = 0;
    if (sl > SEQ - 1) sl = SEQ - 1;
    int nch = sl / SCHUNK + 1;
    int base = (b * NKV + kv) * NCHUNK;

    for (int idx = tid; idx < GQA * HD; idx += 256) {
        int h = idx >> 7, d = idx & (HD - 1);
        float M = -INFINITY;
        for (int c = 0; c < nch; c++) M = fmaxf(M, g_pm[(base + c) * GQA + h]);
        float acc = 0.f, Ls = 0.f;
        for (int c = 0; c < nch; c++) {
            float w = __expf(g_pm[(base + c) * GQA + h] - M);
            acc += w * g_po[((base + c) * GQA + h) * HD + d];
            Ls  += w * g_pl[(base + c) * GQA + h];
        }
        out[b * NH * HD + (kv * GQA + h) * HD + d] = acc / Ls;
    }
}

// ---------------- gate: logits, top4, routing tables ----------------
__global__ __launch_bounds__(256) void gate_k(const float* __restrict__ gw)
{
    int b = blockIdx.x, tid = threadIdx.x, warp = tid >> 5, lane = tid & 31;
    __shared__ float lg[NEXP];
    const float* h = g_h2 + b * HDIM;
    for (int e = warp; e < NEXP; e += 8) {
        const float* g = gw + e * HDIM;
        float s = 0.f;
        for (int i = lane; i < HDIM; i += 32) s += h[i] * g[i];
        for (int o = 16; o; o >>= 1) s += __shfl_xor_sync(0xffffffffu, s, o);
        if (lane == 0) lg[e] = s;
    }
    __syncthreads();
    if (tid == 0) {
        float val[TOPK]; int idx[TOPK];
        unsigned used = 0;
        for (int j = 0; j < TOPK; j++) {
            float best = -1e30f; int bi = 0;
            for (int e = 0; e < NEXP; e++)
                if (!((used >> e) & 1u) && lg[e] > best) { best = lg[e]; bi = e; }
            used |= 1u << bi; val[j] = best; idx[j] = bi;
        }
        float s = 0.f, wj[TOPK];
        for (int j = 0; j < TOPK; j++) { wj[j] = expf(val[j] - val[0]); s += wj[j]; }
        float is = 1.f / s;
        for (int j = 0; j < TOPK; j++) {
            int e = idx[j];
            int pos = atomicAdd(&g_cnt[e], 1);
            g_tok [e * BATCH + pos] = b;
            g_slot[e * BATCH + pos] = j;
            g_wt  [e * BATCH + pos] = wj[j] * is;
        }
    }
}

// ---------------- MoE w1: 4-deep pipelined, BM=16 BN=64 BK=16 ----------------
__global__ __launch_bounds__(256) void moe_w1_k(const float* __restrict__ w1)
{
    int e = blockIdx.y;
    int cnt = g_cnt[e];
    int m0 = blockIdx.z * 16;
    if (m0 >= cnt) return;
    int ib = blockIdx.x * 64;

    __shared__ float As[PD][16][17];
    __shared__ float Gs[PD][16][68];
    __shared__ float Us[PD][16][68];
    __shared__ int toks[16];

    int tid = threadIdx.x;
    if (tid < 16) toks[tid] = (m0 + tid < cnt) ? g_tok[e * BATCH + m0 + tid]
                                               : g_tok[e * BATCH];
    __syncthreads();

    int am = tid >> 4, ak = tid & 15;
    int ln = tid >> 2, lk = (tid & 3) * 4;
    const float* Agp = g_h2 + (long)toks[am] * HDIM + ak;
    const float* Ggp = w1 + ((long)e * 2 * IDIM + ib + ln) * HDIM + lk;
    const float* Ugp = Ggp + (long)IDIM * HDIM;

    int tx = tid & 15, ty = tid >> 4;
    float ag[4] = {}, au[4] = {};

    float  rAa[PD];
    float4 rG[PD], rU[PD];
    const int tiles = HDIM / 16;   // 128
    #pragma unroll
    for (int s = 0; s < PD; s++) {
        rAa[s] = *(Agp + s * 16);
        rG[s]  = *(const float4*)(Ggp + s * 16);
        rU[s]  = *(const float4*)(Ugp + s * 16);
    }

    for (int t = 0; t < tiles; t++) {
        int buf = t & (PD - 1);
        As[buf][ak][am] = rAa[buf];
        Gs[buf][lk+0][ln] = rG[buf].x; Gs[buf][lk+1][ln] = rG[buf].y;
        Gs[buf][lk+2][ln] = rG[buf].z; Gs[buf][lk+3][ln] = rG[buf].w;
        Us[buf][lk+0][ln] = rU[buf].x; Us[buf][lk+1][ln] = rU[buf].y;
        Us[buf][lk+2][ln] = rU[buf].z; Us[buf][lk+3][ln] = rU[buf].w;
        if (t + PD < tiles) {
            rAa[buf] = *(Agp + (t + PD) * 16);
            rG[buf]  = *(const float4*)(Ggp + (t + PD) * 16);
            rU[buf]  = *(const float4*)(Ugp + (t + PD) * 16);
        }
        __syncthreads();
        #pragma unroll
        for (int kk = 0; kk < 16; kk++) {
            float a = As[buf][kk][ty];
            float4 g4 = *(const float4*)&Gs[buf][kk][tx * 4];
            float4 u4 = *(const float4*)&Us[buf][kk][tx * 4];
            ag[0] = fmaf(a, g4.x, ag[0]); ag[1] = fmaf(a, g4.y, ag[1]);
            ag[2] = fmaf(a, g4.z, ag[2]); ag[3] = fmaf(a, g4.w, ag[3]);
            au[0] = fmaf(a, u4.x, au[0]); au[1] = fmaf(a, u4.y, au[1]);
            au[2] = fmaf(a, u4.z, au[2]); au[3] = fmaf(a, u4.w, au[3]);
        }
        __syncthreads();
    }

    int m = m0 + ty;
    if (m < cnt) {
        float4 v;
        float* vp = (float*)&v;
        #pragma unroll
        for (int j = 0; j < 4; j++) {
            float g = ag[j];
            vp[j] = g / (1.f + expf(-g)) * au[j];
        }
        *(float4*)&g_act[(long)(e * BATCH + m) * IDIM + ib + tx * 4] = v;
    }
}

// ---------------- MoE w2: 4-deep pipelined, BM=16 BN=64 BK=16 ----------------
__global__ __launch_bounds__(256) void moe_w2_k(const float* __restrict__ w2)
{
    int e = blockIdx.y;
    int cnt = g_cnt[e];
    int m0 = blockIdx.z * 16;
    if (m0 >= cnt) return;
    int hb = blockIdx.x * 64;

    __shared__ float As[PD][16][17];
    __shared__ float Ws[PD][16][68];

    int tid = threadIdx.x;
    int am = tid >> 4, ak = tid & 15;
    int ln = tid >> 2, lk = (tid & 3) * 4;
    const float* Agp = g_act + (long)(e * BATCH + m0 + am) * IDIM + ak;
    const float* Wgp = w2 + ((long)e * HDIM + hb + ln) * IDIM + lk;

    int tx = tid & 15, ty = tid >> 4;
    float acc[4] = {};

    float  rAa[PD];
    float4 rW[PD];
    const int tiles = IDIM / 16;   // 48
    #pragma unroll
    for (int s = 0; s < PD; s++) {
        rAa[s] = *(Agp + s * 16);
        rW[s]  = *(const float4*)(Wgp + s * 16);
    }

    for (int t = 0; t < tiles; t++) {
        int buf = t & (PD - 1);
        As[buf][ak][am] = rAa[buf];
        Ws[buf][lk+0][ln] = rW[buf].x; Ws[buf][lk+1][ln] = rW[buf].y;
        Ws[buf][lk+2][ln] = rW[buf].z; Ws[buf][lk+3][ln] = rW[buf].w;
        if (t + PD < tiles) {
            rAa[buf] = *(Agp + (t + PD) * 16);
            rW[buf]  = *(const float4*)(Wgp + (t + PD) * 16);
        }
        __syncthreads();
        #pragma unroll
        for (int kk = 0; kk < 16; kk++) {
            float a = As[buf][kk][ty];
            float4 w4 = *(const float4*)&Ws[buf][kk][tx * 4];
            acc[0] = fmaf(a, w4.x, acc[0]); acc[1] = fmaf(a, w4.y, acc[1]);
            acc[2] = fmaf(a, w4.z, acc[2]); acc[3] = fmaf(a, w4.w, acc[3]);
        }
        __syncthreads();
    }

    int m = m0 + ty;
    if (m < cnt) {
        int tok = g_tok [e * BATCH + m];
        int j   = g_slot[e * BATCH + m];
        float w = g_wt  [e * BATCH + m];
        float4 v = make_float4(w * acc[0], w * acc[1], w * acc[2], w * acc[3]);
        *(float4*)&g_ypair[(long)(tok * TOPK + j) * HDIM + hb + tx * 4] = v;
    }
}

// ---------------- finalize: out = hs2 + sum_j ypair ----------------
__global__ __launch_bounds__(256) void finalize_k(float* __restrict__ out)
{
    int idx = blockIdx.x * 256 + threadIdx.x;
    int tok = idx >> 11, hh = idx & (HDIM - 1);
    float s = g_hs2[idx];
    #pragma unroll
    for (int j = 0; j < TOPK; j++) s += g_ypair[(tok * TOPK + j) * HDIM + hh];
    out[idx] = s;
}

// ---------------- launch ----------------
extern "C" void kernel_launch(void* const* d_in, const int* in_sizes, int n_in,
                              void* d_out, int out_size)
{
    static float *p_hn = 0, *p_qkv = 0, *p_attn = 0, *p_hs2 = 0, *p_h2 = 0, *p_part = 0;
    if (!p_hn) {
        cudaGetSymbolAddress((void**)&p_hn,   g_hn);
        cudaGetSymbolAddress((void**)&p_qkv,  g_qkv);
        cudaGetSymbolAddress((void**)&p_attn, g_attn);
        cudaGetSymbolAddress((void**)&p_hs2,  g_hs2);
        cudaGetSymbolAddress((void**)&p_h2,   g_h2);
        cudaGetSymbolAddress((void**)&p_part, g_part);
    }

    const float *hidden = 0, *k_cache = 0, *v_cache = 0, *w_qkv = 0, *b_qkv = 0;
    const float *w_o = 0, *ln1_w = 0, *ln2_w = 0, *gate_w = 0, *w1 = 0, *w2 = 0;
    const int *positions = 0, *seqlens = 0;

    for (int i = 0; i < n_in; i++) {
        long sz = (long)in_sizes[i];
        const void* p = d_in[i];
        if      (sz == (long)BATCH * HDIM)            hidden = (const float*)p;
        else if (sz == (long)BATCH) {
            if (!positions) positions = (const int*)p; else seqlens = (const int*)p;
        }
        else if (sz == (long)BATCH * SEQ * NKV * HD) {
            if (!k_cache) k_cache = (const float*)p; else v_cache = (const float*)p;
        }
        else if (sz == (long)QKV_N * HDIM)            w_qkv  = (const float*)p;
        else if (sz == (long)QKV_N)                   b_qkv  = (const float*)p;
        else if (sz == (long)HDIM * NH * HD)          w_o    = (const float*)p;
        else if (sz == (long)HDIM) {
            if (!ln1_w) ln1_w = (const float*)p; else ln2_w = (const float*)p;
        }
        else if (sz == (long)NEXP * HDIM)             gate_w = (const float*)p;
        else if (sz == (long)NEXP * 2 * IDIM * HDIM)  w1     = (const float*)p;
        else if (sz == (long)NEXP * HDIM * IDIM)      w2     = (const float*)p;
    }
    if (!seqlens && positions) seqlens = positions;
    if (!v_cache) v_cache = k_cache;
    if (!ln2_w)   ln2_w   = ln1_w;

    float* out = (float*)d_out;

    reset_k<<<1, 32>>>();
    rmsnorm_k<<<BATCH, 256>>>(hidden, ln1_w, p_hn);
    gemm_part_k<<<dim3(QKV_N / 64, 4), 256>>>(p_hn, w_qkv, p_part, QKV_N, HDIM, 4);
    gemm_reduce_k<<<(64 * QKV_N) / 1024, 256>>>(p_part, b_qkv, nullptr, p_qkv, QKV_N, 4);
    attn_part_k<<<dim3(NCHUNK, NKV, BATCH), 256>>>(k_cache, v_cache, seqlens);
    attn_comb_k<<<BATCH * NKV, 256>>>(seqlens, p_attn);
    gemm_part_k<<<dim3(HDIM / 64, 8), 256>>>(p_attn, w_o, p_part, HDIM, NH * HD, 8);
    gemm_reduce_k<<<(64 * HDIM) / 1024, 256>>>(p_part, nullptr, hidden, p_hs2, HDIM, 8);
    rmsnorm_k<<<BATCH, 256>>>(p_hs2, ln2_w, p_h2);
    gate_k<<<BATCH, 256>>>(gate_w);
    moe_w1_k<<<dim3(IDIM / 64, NEXP, 4), 256>>>(w1);
    moe_w2_k<<<dim3(HDIM / 64, NEXP, 4), 256>>>(w2);
    finalize_k<<<(BATCH * HDIM) / 256, 256>>>(out);
}

// round 10
// speedup vs baseline: 1.4361x; 1.4361x over previous
#include <cuda_runtime.h>
#include <cuda_bf16.h>
#include <math.h>

// ---------------- problem constants ----------------
#define BATCH 64
#define HDIM  2048
#define SEQ   2048
#define NH    32
#define NKV   4
#define GQA   8          // NH/NKV
#define HD    128
#define NEXP  32
#define IDIM  768
#define TOPK  4
#define QKV_N 5120       // (NH+2*NKV)*HD
#define EPS   1e-6f
#define SCHUNK 256
#define NCHUNK (SEQ / SCHUNK)   // 8
#define PD 4                    // GEMM pipeline depth (STATIC unroll)

// ---------------- scratch (device globals) ----------------
// Scratch passed as kernel ARGUMENTS must be resolved via cudaGetSymbolAddress
// (host &g_x is the ATS host shadow — rounds 1-5 bug). In-kernel refs ok.
__device__ float g_hn   [BATCH * HDIM];
__device__ float g_qkv  [BATCH * QKV_N];
__device__ float g_attn [BATCH * NH * HD];
__device__ float g_hs2  [BATCH * HDIM];
__device__ float g_h2   [BATCH * HDIM];
__device__ float g_act  [NEXP * BATCH * IDIM];
__device__ float g_ypair[BATCH * TOPK * HDIM];
__device__ float g_part [8 * BATCH * QKV_N / 2];
__device__ int   g_cnt  [NEXP];
__device__ int   g_tok  [NEXP * BATCH];
__device__ int   g_slot [NEXP * BATCH];
__device__ float g_wt   [NEXP * BATCH];
// split-S attention partials
__device__ float g_pm [BATCH * NKV * NCHUNK * GQA];
__device__ float g_pl [BATCH * NKV * NCHUNK * GQA];
__device__ float g_po [BATCH * NKV * NCHUNK * GQA * HD];

// ---------------- reset routing counters ----------------
__global__ void reset_k() {
    if (threadIdx.x < NEXP) g_cnt[threadIdx.x] = 0;
}

// ---------------- RMSNorm (block per token) ----------------
__global__ __launch_bounds__(256) void rmsnorm_k(
    const float* __restrict__ x, const float* __restrict__ w, float* __restrict__ y)
{
    int b = blockIdx.x, tid = threadIdx.x;
    const float* xb = x + b * HDIM;
    float s = 0.f;
    for (int i = tid; i < HDIM; i += 256) { float v = xb[i]; s += v * v; }
    for (int o = 16; o; o >>= 1) s += __shfl_xor_sync(0xffffffffu, s, o);
    __shared__ float red[8];
    __shared__ float inv;
    if ((tid & 31) == 0) red[tid >> 5] = s;
    __syncthreads();
    if (tid == 0) {
        float t = 0.f;
        #pragma unroll
        for (int i = 0; i < 8; i++) t += red[i];
        inv = rsqrtf(t * (1.f / HDIM) + EPS);
    }
    __syncthreads();
    float iv = inv;
    for (int i = tid; i < HDIM; i += 256) y[b * HDIM + i] = xb[i] * iv * w[i];
}

// ---------------- GEMM partial: static 4-deep pipeline, BM=64 BN=64 BK=16 -------
// tiles (= K/ksplit/16) MUST be a multiple of PD (holds: 32, 32).
__global__ __launch_bounds__(256) void gemm_part_k(
    const float* __restrict__ A, const float* __restrict__ W,
    float* __restrict__ part, int N, int K, int ksplit)
{
    __shared__ float As[PD][16][68];
    __shared__ float Ws[PD][16][68];
    int nb = blockIdx.x * 64;
    int ks = blockIdx.y;
    int klen = K / ksplit;
    int kbeg = ks * klen;
    int tiles = klen / 16;
    int tid = threadIdx.x;

    int lm = tid >> 2;            // 0..63
    int lk = (tid & 3) * 4;       // 0,4,8,12
    const float* Ag = A + (long)lm * K + kbeg + lk;
    const float* Wg = W + (long)(nb + lm) * K + kbeg + lk;

    int tx = tid & 15, ty = tid >> 4;
    float acc[4][4] = {};

    float4 rA[PD], rW[PD];
    #pragma unroll
    for (int s = 0; s < PD; s++) {
        rA[s] = *(const float4*)(Ag + s * 16);
        rW[s] = *(const float4*)(Wg + s * 16);
    }

    for (int t = 0; t < tiles; t += PD) {
        #pragma unroll
        for (int p = 0; p < PD; p++) {           // p is compile-time after unroll
            As[p][lk+0][lm] = rA[p].x; As[p][lk+1][lm] = rA[p].y;
            As[p][lk+2][lm] = rA[p].z; As[p][lk+3][lm] = rA[p].w;
            Ws[p][lk+0][lm] = rW[p].x; Ws[p][lk+1][lm] = rW[p].y;
            Ws[p][lk+2][lm] = rW[p].z; Ws[p][lk+3][lm] = rW[p].w;
            if (t + p + PD < tiles) {
                rA[p] = *(const float4*)(Ag + (t + p + PD) * 16);
                rW[p] = *(const float4*)(Wg + (t + p + PD) * 16);
            }
            __syncthreads();
            #pragma unroll
            for (int kk = 0; kk < 16; kk++) {
                float4 a = *(const float4*)&As[p][kk][ty * 4];
                float4 w = *(const float4*)&Ws[p][kk][tx * 4];
                acc[0][0] = fmaf(a.x, w.x, acc[0][0]); acc[0][1] = fmaf(a.x, w.y, acc[0][1]);
                acc[0][2] = fmaf(a.x, w.z, acc[0][2]); acc[0][3] = fmaf(a.x, w.w, acc[0][3]);
                acc[1][0] = fmaf(a.y, w.x, acc[1][0]); acc[1][1] = fmaf(a.y, w.y, acc[1][1]);
                acc[1][2] = fmaf(a.y, w.z, acc[1][2]); acc[1][3] = fmaf(a.y, w.w, acc[1][3]);
                acc[2][0] = fmaf(a.z, w.x, acc[2][0]); acc[2][1] = fmaf(a.z, w.y, acc[2][1]);
                acc[2][2] = fmaf(a.z, w.z, acc[2][2]); acc[2][3] = fmaf(a.z, w.w, acc[2][3]);
                acc[3][0] = fmaf(a.w, w.x, acc[3][0]); acc[3][1] = fmaf(a.w, w.y, acc[3][1]);
                acc[3][2] = fmaf(a.w, w.z, acc[3][2]); acc[3][3] = fmaf(a.w, w.w, acc[3][3]);
            }
            __syncthreads();
        }
    }

    #pragma unroll
    for (int i = 0; i < 4; i++) {
        float4 v = make_float4(acc[i][0], acc[i][1], acc[i][2], acc[i][3]);
        *(float4*)&part[((long)(ks * 64 + ty * 4 + i)) * N + nb + tx * 4] = v;
    }
}

// ---------------- GEMM reduce: C = sum_ks part + bias (+res) ----------------
__global__ __launch_bounds__(256) void gemm_reduce_k(
    const float* __restrict__ part, const float* __restrict__ bias,
    const float* __restrict__ res, float* __restrict__ C, int N, int ksplit)
{
    int idx = (blockIdx.x * 256 + threadIdx.x) * 4;
    int m = idx / N, n = idx % N;
    float4 s = bias ? *(const float4*)&bias[n] : make_float4(0.f, 0.f, 0.f, 0.f);
    for (int ks = 0; ks < ksplit; ks++) {
        float4 p = *(const float4*)&part[((long)(ks * 64 + m)) * N + n];
        s.x += p.x; s.y += p.y; s.z += p.z; s.w += p.w;
    }
    if (res) {
        float4 r = *(const float4*)&res[idx];
        s.x += r.x; s.y += r.y; s.z += r.z; s.w += r.w;
    }
    *(float4*)&C[idx] = s;
}

// ---------------- split-S GQA flash-decode: partial per (b, kv, chunk) ----------------
__global__ __launch_bounds__(256) void attn_part_k(
    const float* __restrict__ kc, const float* __restrict__ vc,
    const int* __restrict__ seq_lens)
{
    int c  = blockIdx.x;
    int kv = blockIdx.y;
    int b  = blockIdx.z;
    int tid = threadIdx.x, warp = tid >> 5, lane = tid & 31;
    int sl = seq_lens[b];
    if (sl < 0) sl = 0;
    if (sl > SEQ - 1) sl = SEQ - 1;
    int L  = sl + 1;
    int s0 = c * SCHUNK;
    if (s0 >= L) return;
    int s1 = s0 + SCHUNK; if (s1 > L) s1 = L;
    const float scale = 0.08838834764831845f;

    const float* qbase = g_qkv + b * QKV_N + kv * GQA * HD;
    const float* knew  = g_qkv + b * QKV_N + NH * HD + kv * HD;
    const float* vnew  = g_qkv + b * QKV_N + (NH + NKV) * HD + kv * HD;

    float4 q[GQA];
    #pragma unroll
    for (int h = 0; h < GQA; h++) q[h] = *(const float4*)(qbase + h * HD + lane * 4);

    float m[GQA], l[GQA];
    float4 o[GQA];
    #pragma unroll
    for (int h = 0; h < GQA; h++) {
        m[h] = -INFINITY; l[h] = 0.f; o[h] = make_float4(0.f, 0.f, 0.f, 0.f);
    }

    int s = s0 + warp;
    if (s < s1) {
        const float* kp = (s == sl) ? knew : (kc + ((size_t)(b * SEQ + s) * NKV + kv) * HD);
        const float* vp = (s == sl) ? vnew : (vc + ((size_t)(b * SEQ + s) * NKV + kv) * HD);
        float4 kk = *(const float4*)(kp + lane * 4);
        float4 vv = *(const float4*)(vp + lane * 4);
        for (;;) {
            int sn = s + 8;
            float4 knx, vnx;
            if (sn < s1) {
                const float* kp2 = (sn == sl) ? knew : (kc + ((size_t)(b * SEQ + sn) * NKV + kv) * HD);
                const float* vp2 = (sn == sl) ? vnew : (vc + ((size_t)(b * SEQ + sn) * NKV + kv) * HD);
                knx = *(const float4*)(kp2 + lane * 4);
                vnx = *(const float4*)(vp2 + lane * 4);
            }
            #pragma unroll
            for (int h = 0; h < GQA; h++) {
                float d = q[h].x * kk.x + q[h].y * kk.y + q[h].z * kk.z + q[h].w * kk.w;
                d += __shfl_xor_sync(0xffffffffu, d, 16);
                d += __shfl_xor_sync(0xffffffffu, d, 8);
                d += __shfl_xor_sync(0xffffffffu, d, 4);
                d += __shfl_xor_sync(0xffffffffu, d, 2);
                d += __shfl_xor_sync(0xffffffffu, d, 1);
                float sc = d * scale;
                float nm = fmaxf(m[h], sc);
                float corr = __expf(m[h] - nm);
                float p = __expf(sc - nm);
                l[h] = l[h] * corr + p;
                o[h].x = o[h].x * corr + p * vv.x;
                o[h].y = o[h].y * corr + p * vv.y;
                o[h].z = o[h].z * corr + p * vv.z;
                o[h].w = o[h].w * corr + p * vv.w;
                m[h] = nm;
            }
            if (sn >= s1) break;
            s = sn; kk = knx; vv = vnx;
        }
    }

    __shared__ float sm[8][GQA], sll[8][GQA];
    __shared__ float so[8][GQA][HD];
    #pragma unroll
    for (int h = 0; h < GQA; h++) {
        if (lane == 0) { sm[warp][h] = m[h]; sll[warp][h] = l[h]; }
        *(float4*)&so[warp][h][lane * 4] = o[h];
    }
    __syncthreads();

    int pbase = ((b * NKV + kv) * NCHUNK + c) * GQA;
    for (int idx = tid; idx < GQA * HD; idx += 256) {
        int h = idx >> 7, d = idx & (HD - 1);
        float M = -INFINITY;
        #pragma unroll
        for (int w = 0; w < 8; w++) M = fmaxf(M, sm[w][h]);
        float acc = 0.f, Ls = 0.f;
        #pragma unroll
        for (int w = 0; w < 8; w++) {
            float cw = __expf(sm[w][h] - M);
            acc += cw * so[w][h][d];
            Ls  += cw * sll[w][h];
        }
        g_po[(pbase + h) * HD + d] = acc;
        if (d == 0) { g_pm[pbase + h] = M; g_pl[pbase + h] = Ls; }
    }
}

// ---------------- combine split-S partials ----------------
__global__ __launch_bounds__(256) void attn_comb_k(
    const int* __restrict__ seq_lens, float* __restrict__ out)
{
    int b  = blockIdx.x >> 2;
    int kv = blockIdx.x & 3;
    int tid = threadIdx.x;
    int sl = seq_lens[b];
    if (sl < 0) sl = 0;
    if (sl > SEQ - 1) sl = SEQ - 1;
    int nch = sl / SCHUNK + 1;
    int base = (b * NKV + kv) * NCHUNK;

    for (int idx = tid; idx < GQA * HD; idx += 256) {
        int h = idx >> 7, d = idx & (HD - 1);
        float M = -INFINITY;
        for (int c = 0; c < nch; c++) M = fmaxf(M, g_pm[(base + c) * GQA + h]);
        float acc = 0.f, Ls = 0.f;
        for (int c = 0; c < nch; c++) {
            float w = __expf(g_pm[(base + c) * GQA + h] - M);
            acc += w * g_po[((base + c) * GQA + h) * HD + d];
            Ls  += w * g_pl[(base + c) * GQA + h];
        }
        out[b * NH * HD + (kv * GQA + h) * HD + d] = acc / Ls;
    }
}

// ---------------- gate: logits, top4, routing tables ----------------
__global__ __launch_bounds__(256) void gate_k(const float* __restrict__ gw)
{
    int b = blockIdx.x, tid = threadIdx.x, warp = tid >> 5, lane = tid & 31;
    __shared__ float lg[NEXP];
    const float* h = g_h2 + b * HDIM;
    for (int e = warp; e < NEXP; e += 8) {
        const float* g = gw + e * HDIM;
        float s = 0.f;
        for (int i = lane; i < HDIM; i += 32) s += h[i] * g[i];
        for (int o = 16; o; o >>= 1) s += __shfl_xor_sync(0xffffffffu, s, o);
        if (lane == 0) lg[e] = s;
    }
    __syncthreads();
    if (tid == 0) {
        float val[TOPK]; int idx[TOPK];
        unsigned used = 0;
        for (int j = 0; j < TOPK; j++) {
            float best = -1e30f; int bi = 0;
            for (int e = 0; e < NEXP; e++)
                if (!((used >> e) & 1u) && lg[e] > best) { best = lg[e]; bi = e; }
            used |= 1u << bi; val[j] = best; idx[j] = bi;
        }
        float s = 0.f, wj[TOPK];
        for (int j = 0; j < TOPK; j++) { wj[j] = expf(val[j] - val[0]); s += wj[j]; }
        float is = 1.f / s;
        for (int j = 0; j < TOPK; j++) {
            int e = idx[j];
            int pos = atomicAdd(&g_cnt[e], 1);
            g_tok [e * BATCH + pos] = b;
            g_slot[e * BATCH + pos] = j;
            g_wt  [e * BATCH + pos] = wj[j] * is;
        }
    }
}

// ---------------- MoE w1: static 4-deep pipeline, BM=16 BN=64 BK=16 ----------------
// tiles = HDIM/16 = 128 (mult of PD)
__global__ __launch_bounds__(256) void moe_w1_k(const float* __restrict__ w1)
{
    int e = blockIdx.y;
    int cnt = g_cnt[e];
    int m0 = blockIdx.z * 16;
    if (m0 >= cnt) return;
    int ib = blockIdx.x * 64;

    __shared__ float As[PD][16][17];
    __shared__ float Gs[PD][16][68];
    __shared__ float Us[PD][16][68];
    __shared__ int toks[16];

    int tid = threadIdx.x;
    if (tid < 16) toks[tid] = (m0 + tid < cnt) ? g_tok[e * BATCH + m0 + tid]
                                               : g_tok[e * BATCH];
    __syncthreads();

    int am = tid >> 4, ak = tid & 15;
    int ln = tid >> 2, lk = (tid & 3) * 4;
    const float* Agp = g_h2 + (long)toks[am] * HDIM + ak;
    const float* Ggp = w1 + ((long)e * 2 * IDIM + ib + ln) * HDIM + lk;
    const float* Ugp = Ggp + (long)IDIM * HDIM;

    int tx = tid & 15, ty = tid >> 4;
    float ag[4] = {}, au[4] = {};

    float  rAa[PD];
    float4 rG[PD], rU[PD];
    const int tiles = HDIM / 16;   // 128
    #pragma unroll
    for (int s = 0; s < PD; s++) {
        rAa[s] = *(Agp + s * 16);
        rG[s]  = *(const float4*)(Ggp + s * 16);
        rU[s]  = *(const float4*)(Ugp + s * 16);
    }

    for (int t = 0; t < tiles; t += PD) {
        #pragma unroll
        for (int p = 0; p < PD; p++) {
            As[p][ak][am] = rAa[p];
            Gs[p][lk+0][ln] = rG[p].x; Gs[p][lk+1][ln] = rG[p].y;
            Gs[p][lk+2][ln] = rG[p].z; Gs[p][lk+3][ln] = rG[p].w;
            Us[p][lk+0][ln] = rU[p].x; Us[p][lk+1][ln] = rU[p].y;
            Us[p][lk+2][ln] = rU[p].z; Us[p][lk+3][ln] = rU[p].w;
            if (t + p + PD < tiles) {
                rAa[p] = *(Agp + (t + p + PD) * 16);
                rG[p]  = *(const float4*)(Ggp + (t + p + PD) * 16);
                rU[p]  = *(const float4*)(Ugp + (t + p + PD) * 16);
            }
            __syncthreads();
            #pragma unroll
            for (int kk = 0; kk < 16; kk++) {
                float a = As[p][kk][ty];
                float4 g4 = *(const float4*)&Gs[p][kk][tx * 4];
                float4 u4 = *(const float4*)&Us[p][kk][tx * 4];
                ag[0] = fmaf(a, g4.x, ag[0]); ag[1] = fmaf(a, g4.y, ag[1]);
                ag[2] = fmaf(a, g4.z, ag[2]); ag[3] = fmaf(a, g4.w, ag[3]);
                au[0] = fmaf(a, u4.x, au[0]); au[1] = fmaf(a, u4.y, au[1]);
                au[2] = fmaf(a, u4.z, au[2]); au[3] = fmaf(a, u4.w, au[3]);
            }
            __syncthreads();
        }
    }

    int m = m0 + ty;
    if (m < cnt) {
        float4 v;
        float* vp = (float*)&v;
        #pragma unroll
        for (int j = 0; j < 4; j++) {
            float g = ag[j];
            vp[j] = g / (1.f + expf(-g)) * au[j];
        }
        *(float4*)&g_act[(long)(e * BATCH + m) * IDIM + ib + tx * 4] = v;
    }
}

// ---------------- MoE w2: static 4-deep pipeline, BM=16 BN=64 BK=16 ----------------
// tiles = IDIM/16 = 48 (mult of PD)
__global__ __launch_bounds__(256) void moe_w2_k(const float* __restrict__ w2)
{
    int e = blockIdx.y;
    int cnt = g_cnt[e];
    int m0 = blockIdx.z * 16;
    if (m0 >= cnt) return;
    int hb = blockIdx.x * 64;

    __shared__ float As[PD][16][17];
    __shared__ float Ws[PD][16][68];

    int tid = threadIdx.x;
    int am = tid >> 4, ak = tid & 15;
    int ln = tid >> 2, lk = (tid & 3) * 4;
    const float* Agp = g_act + (long)(e * BATCH + m0 + am) * IDIM + ak;
    const float* Wgp = w2 + ((long)e * HDIM + hb + ln) * IDIM + lk;

    int tx = tid & 15, ty = tid >> 4;
    float acc[4] = {};

    float  rAa[PD];
    float4 rW[PD];
    const int tiles = IDIM / 16;   // 48
    #pragma unroll
    for (int s = 0; s < PD; s++) {
        rAa[s] = *(Agp + s * 16);
        rW[s]  = *(const float4*)(Wgp + s * 16);
    }

    for (int t = 0; t < tiles; t += PD) {
        #pragma unroll
        for (int p = 0; p < PD; p++) {
            As[p][ak][am] = rAa[p];
            Ws[p][lk+0][ln] = rW[p].x; Ws[p][lk+1][ln] = rW[p].y;
            Ws[p][lk+2][ln] = rW[p].z; Ws[p][lk+3][ln] = rW[p].w;
            if (t + p + PD < tiles) {
                rAa[p] = *(Agp + (t + p + PD) * 16);
                rW[p]  = *(const float4*)(Wgp + (t + p + PD) * 16);
            }
            __syncthreads();
            #pragma unroll
            for (int kk = 0; kk < 16; kk++) {
                float a = As[p][kk][ty];
                float4 w4 = *(const float4*)&Ws[p][kk][tx * 4];
                acc[0] = fmaf(a, w4.x, acc[0]); acc[1] = fmaf(a, w4.y, acc[1]);
                acc[2] = fmaf(a, w4.z, acc[2]); acc[3] = fmaf(a, w4.w, acc[3]);
            }
            __syncthreads();
        }
    }

    int m = m0 + ty;
    if (m < cnt) {
        int tok = g_tok [e * BATCH + m];
        int j   = g_slot[e * BATCH + m];
        float w = g_wt  [e * BATCH + m];
        float4 v = make_float4(w * acc[0], w * acc[1], w * acc[2], w * acc[3]);
        *(float4*)&g_ypair[(long)(tok * TOPK + j) * HDIM + hb + tx * 4] = v;
    }
}

// ---------------- finalize: out = hs2 + sum_j ypair ----------------
__global__ __launch_bounds__(256) void finalize_k(float* __restrict__ out)
{
    int idx = blockIdx.x * 256 + threadIdx.x;
    int tok = idx >> 11, hh = idx & (HDIM - 1);
    float s = g_hs2[idx];
    #pragma unroll
    for (int j = 0; j < TOPK; j++) s += g_ypair[(tok * TOPK + j) * HDIM + hh];
    out[idx] = s;
}

// ---------------- launch ----------------
extern "C" void kernel_launch(void* const* d_in, const int* in_sizes, int n_in,
                              void* d_out, int out_size)
{
    static float *p_hn = 0, *p_qkv = 0, *p_attn = 0, *p_hs2 = 0, *p_h2 = 0, *p_part = 0;
    if (!p_hn) {
        cudaGetSymbolAddress((void**)&p_hn,   g_hn);
        cudaGetSymbolAddress((void**)&p_qkv,  g_qkv);
        cudaGetSymbolAddress((void**)&p_attn, g_attn);
        cudaGetSymbolAddress((void**)&p_hs2,  g_hs2);
        cudaGetSymbolAddress((void**)&p_h2,   g_h2);
        cudaGetSymbolAddress((void**)&p_part, g_part);
    }

    const float *hidden = 0, *k_cache = 0, *v_cache = 0, *w_qkv = 0, *b_qkv = 0;
    const float *w_o = 0, *ln1_w = 0, *ln2_w = 0, *gate_w = 0, *w1 = 0, *w2 = 0;
    const int *positions = 0, *seqlens = 0;

    for (int i = 0; i < n_in; i++) {
        long sz = (long)in_sizes[i];
        const void* p = d_in[i];
        if      (sz == (long)BATCH * HDIM)            hidden = (const float*)p;
        else if (sz == (long)BATCH) {
            if (!positions) positions = (const int*)p; else seqlens = (const int*)p;
        }
        else if (sz == (long)BATCH * SEQ * NKV * HD) {
            if (!k_cache) k_cache = (const float*)p; else v_cache = (const float*)p;
        }
        else if (sz == (long)QKV_N * HDIM)            w_qkv  = (const float*)p;
        else if (sz == (long)QKV_N)                   b_qkv  = (const float*)p;
        else if (sz == (long)HDIM * NH * HD)          w_o    = (const float*)p;
        else if (sz == (long)HDIM) {
            if (!ln1_w) ln1_w = (const float*)p; else ln2_w = (const float*)p;
        }
        else if (sz == (long)NEXP * HDIM)             gate_w = (const float*)p;
        else if (sz == (long)NEXP * 2 * IDIM * HDIM)  w1     = (const float*)p;
        else if (sz == (long)NEXP * HDIM * IDIM)      w2     = (const float*)p;
    }
    if (!seqlens && positions) seqlens = positions;
    if (!v_cache) v_cache = k_cache;
    if (!ln2_w)   ln2_w   = ln1_w;

    float* out = (float*)d_out;

    reset_k<<<1, 32>>>();
    rmsnorm_k<<<BATCH, 256>>>(hidden, ln1_w, p_hn);
    gemm_part_k<<<dim3(QKV_N / 64, 4), 256>>>(p_hn, w_qkv, p_part, QKV_N, HDIM, 4);
    gemm_reduce_k<<<(64 * QKV_N) / 1024, 256>>>(p_part, b_qkv, nullptr, p_qkv, QKV_N, 4);
    attn_part_k<<<dim3(NCHUNK, NKV, BATCH), 256>>>(k_cache, v_cache, seqlens);
    attn_comb_k<<<BATCH * NKV, 256>>>(seqlens, p_attn);
    gemm_part_k<<<dim3(HDIM / 64, 8), 256>>>(p_attn, w_o, p_part, HDIM, NH * HD, 8);
    gemm_reduce_k<<<(64 * HDIM) / 1024, 256>>>(p_part, nullptr, hidden, p_hs2, HDIM, 8);
    rmsnorm_k<<<BATCH, 256>>>(p_hs2, ln2_w, p_h2);
    gate_k<<<BATCH, 256>>>(gate_w);
    moe_w1_k<<<dim3(IDIM / 64, NEXP, 4), 256>>>(w1);
    moe_w2_k<<<dim3(HDIM / 64, NEXP, 4), 256>>>(w2);
    finalize_k<<<(BATCH * HDIM) / 256, 256>>>(out);
}